// round 5
// baseline (speedup 1.0000x reference)
#include <cuda_runtime.h>
#include <math.h>

#define D     256
#define N0    1500
#define N1    1200
#define CATC  600
#define W96   96
#define NPIX  (N0*W96)      /* 144000 */
#define HID   256
#define H2    128

/* ---------------- device scratch ----------------------------------------- */
__device__ float    g_s0[D];
__device__ float    g_acc0[D];
__device__ float    g_accH[D];
__device__ float    g_accL[D];
__device__ float    g_t[W96];
__device__ float    g_tsort[W96];
__device__ int      g_tperm[W96];
__device__ float    g_meanH;
__device__ float    g_W1t[512*256];     /* W1 [k][o] fp32                   */
__device__ float    g_x [N0*D];
__device__ float    g_m0[N0*D];
__device__ float    g_m1[N0*D];
__device__ float    g_u [N0*D];
__device__ float    g_sv [3*N0*256];    /* sorted x/m0/m1 values            */
__device__ int      g_scn[3*N0*256];    /* channel perm of the sort         */
__device__ float    g_c1[(size_t)NPIX*HID];  /* relu(conv1) [pix][o]        */
__device__ float    g_sum1[HID];
__device__ float    g_sq1[HID];
__device__ float    g_sum2[H2];
__device__ float    g_sq2[H2];
__device__ unsigned g_W2p[H2*D];        /* folded W2 [o][c] tf32 bits       */
__device__ float    g_b2p[H2];
__device__ float    g_a2[H2];
__device__ float    g_be2[H2];

__device__ __forceinline__ float sigm(float v) { return 1.f/(1.f+expf(-v)); }
__device__ __forceinline__ unsigned f2tf(float f) {
    unsigned u; asm("cvt.rna.tf32.f32 %0, %1;" : "=r"(u) : "f"(f)); return u;
}
__device__ __forceinline__ void mma8(float c[4], unsigned a0, unsigned a1,
                                     unsigned a2, unsigned a3,
                                     unsigned b0, unsigned b1) {
    asm("mma.sync.aligned.m16n8k8.row.col.f32.tf32.tf32.f32 "
        "{%0,%1,%2,%3},{%4,%5,%6,%7},{%8,%9},{%0,%1,%2,%3};"
        : "+f"(c[0]),"+f"(c[1]),"+f"(c[2]),"+f"(c[3])
        : "r"(a0),"r"(a1),"r"(a2),"r"(a3),"r"(b0),"r"(b1));
}

/* ---------------- zero accumulators -------------------------------------- */
__global__ void k_zero() {
    int t = threadIdx.x;
    g_acc0[t]=0.f; g_accH[t]=0.f; g_accL[t]=0.f;
    g_sum1[t]=0.f; g_sq1[t]=0.f;
    if (t < H2) { g_sum2[t]=0.f; g_sq2[t]=0.f; }
}

/* ---------------- transpose W1 -> [k][o] ---------------------------------- */
__global__ void k_tr(const float* __restrict__ W1) {
    int c = blockIdx.x, o = threadIdx.x;
    g_W1t[c*256 + o] = W1[o*512 + c];
}

/* ---------------- channel-mean accumulation ------------------------------- */
__global__ void k_accum(const float* __restrict__ z0, const float* __restrict__ z1) {
    int b = blockIdx.x, c = threadIdx.x;
    float acc = 0.f;
    if (b < 50) {
        int r0 = b*30;
        #pragma unroll 6
        for (int i=0;i<30;i++) acc += z0[(r0+i)*D + c];
        atomicAdd(&g_acc0[c], acc);
    } else {
        int r0 = (b-50)*30;
        #pragma unroll 6
        for (int i=0;i<30;i++) acc += z1[(r0+i)*D + c];
        if (r0 < CATC) atomicAdd(&g_accH[c], acc);
        else           atomicAdd(&g_accL[c], acc);
    }
}

/* ---------------- small prep: s0, hm, lm, meanH, sorted tau --------------- */
__global__ void k_prep(const float* __restrict__ z1,
                       const float* __restrict__ w1, const float* __restrict__ w2,
                       const float* __restrict__ w3, const float* __restrict__ w4,
                       const float* __restrict__ w5,
                       const int* __restrict__ cdrH, const int* __restrict__ cdrL,
                       const int* __restrict__ notH, const int* __restrict__ notL,
                       int nHc, int nLc, int nHn, int nLn) {
    __shared__ float y0[D];
    __shared__ float av[W96];
    __shared__ float bv[CATC];
    __shared__ float red[256];
    int t = threadIdx.x;

    y0[t] = g_acc0[t] * (1.f/N0);
    __syncthreads();
    {
        float a = 0.f;
        #pragma unroll
        for (int k=0;k<5;k++) { int cc=t+k-2; if (cc>=0 && cc<D) a += w1[k]*y0[cc]; }
        g_s0[t] = sigm(a);
    }

    float sH0;
    {
        float yh0=g_accH[0]*(1.f/CATC), yh1=g_accH[1]*(1.f/CATC), yh2=g_accH[2]*(1.f/CATC);
        sH0 = sigm(w2[2]*yh0 + w2[3]*yh1 + w2[4]*yh2);
    }
    if (t < nHc) av[t] = z1[cdrH[t]*D] * sH0;
    for (int j=t; j<nHn; j+=256) bv[j] = z1[notH[j]*D] * sH0;
    __syncthreads();
    float msumH = 0.f;
    if (t < nHc) { float ai=av[t]; for (int j=0;j<nHn;j++) msumH += fabsf(ai - bv[j]); }
    red[t] = (t<nHc)? msumH : 0.f;
    __syncthreads();
    for (int m=128;m>0;m>>=1){ if(t<m) red[t]+=red[t+m]; __syncthreads(); }
    float gH = sigm(w4[2] * red[0] / ((float)nHc*(float)nHn));
    float myhm = (t<nHc) ? gH * msumH / (float)nHn : 0.f;
    if (t < nHc) g_t[t] = myhm;
    __syncthreads();

    float sL0;
    {
        float yl0=g_accL[0]*(1.f/CATC), yl1=g_accL[1]*(1.f/CATC), yl2=g_accL[2]*(1.f/CATC);
        sL0 = sigm(w3[2]*yl0 + w3[3]*yl1 + w3[4]*yl2);
    }
    if (t < nLc) av[t] = z1[(CATC+cdrL[t])*D] * sL0;
    for (int j=t; j<nLn; j+=256) bv[j] = z1[(CATC+notL[j])*D] * sL0;
    __syncthreads();
    float msumL = 0.f;
    if (t < nLc) { float ai=av[t]; for (int j=0;j<nLn;j++) msumL += fabsf(ai - bv[j]); }
    red[t] = (t<nLc)? msumL : 0.f;
    __syncthreads();
    for (int m=128;m>0;m>>=1){ if(t<m) red[t]+=red[t+m]; __syncthreads(); }
    float gL = sigm(w5[2] * red[0] / ((float)nLc*(float)nLn));
    if (t < nLc) g_t[nHc + t] = gL * msumL / (float)nLn;
    __syncthreads();

    red[t] = myhm;
    __syncthreads();
    for (int m=128;m>0;m>>=1){ if(t<m) red[t]+=red[t+m]; __syncthreads(); }
    if (t==0) g_meanH = red[0] / (float)nHc;
    __syncthreads();

    /* rank-sort tau (stable) for both sides */
    if (t < nHc) {
        float v = g_t[t]; int r = 0;
        for (int j=0;j<nHc;j++) { float vj = g_t[j]; r += (vj < v) || (vj == v && j < t); }
        g_tsort[r] = v; g_tperm[r] = t;
    }
    if (t < nLc) {
        float v = g_t[nHc+t]; int r = 0;
        for (int j=0;j<nLc;j++) { float vj = g_t[nHc+j]; r += (vj < v) || (vj == v && j < t); }
        g_tsort[nHc+r] = v; g_tperm[nHc+r] = t;
    }
}

/* ---------------- per-h vectors x, m0, m1 and u = W1hi . x ---------------- */
#define HB 10
__global__ __launch_bounds__(256) void k_pre2(const float* __restrict__ z0, int nHc) {
    __shared__ float xsall[HB][D];
    __shared__ float ts[W96];
    const int t = threadIdx.x;
    const int hbase = blockIdx.x * HB;
    if (t < W96) ts[t] = g_t[t];
    const float s0 = g_s0[t];
    const float mh = g_meanH;
    const float inv = 1.f / (float)nHc;
    __syncthreads();
    #pragma unroll
    for (int hh=0; hh<HB; hh++) {
        int h = hbase + hh;
        float x = z0[h*D + t] * s0;
        xsall[hh][t] = x;
        g_x [h*D + t] = x;
        float s = 0.f;
        for (int k=0;k<nHc;k++) s += fabsf(x - ts[k]);
        g_m0[h*D + t] = s * inv;
        g_m1[h*D + t] = x * mh;
    }
    __syncthreads();
    float u[HB];
    #pragma unroll
    for (int hh=0;hh<HB;hh++) u[hh]=0.f;
    for (int c=0;c<D;c++) {
        float wv = g_W1t[(256+c)*256 + t];
        #pragma unroll
        for (int hh=0;hh<HB;hh++) u[hh] = fmaf(wv, xsall[hh][c], u[hh]);
    }
    #pragma unroll
    for (int hh=0;hh<HB;hh++) g_u[(hbase+hh)*D + t] = u[hh];
}

/* ---------------- bitonic sort of per-h vectors --------------------------- */
__global__ void k_sort() {
    __shared__ float v[256];
    __shared__ int   ix[256];
    const int h = blockIdx.x, which = blockIdx.y, t = threadIdx.x;
    const float* src = (which == 0) ? g_x : (which == 1) ? g_m0 : g_m1;
    v[t] = src[h*256 + t]; ix[t] = t;
    __syncthreads();
    for (int k=2;k<=256;k<<=1) {
        for (int jj=k>>1; jj>0; jj>>=1) {
            int p = t ^ jj;
            if (p > t) {
                bool asc = ((t & k) == 0);
                float a = v[t], b = v[p];
                bool sw = asc ? (a > b) : (a < b);
                if (sw) {
                    v[t] = b; v[p] = a;
                    int tmp = ix[t]; ix[t] = ix[p]; ix[p] = tmp;
                }
            }
            __syncthreads();
        }
    }
    g_sv [(which*N0 + h)*256 + t] = v[t];
    g_scn[(which*N0 + h)*256 + t] = ix[t];
}

/* ---------------- sweep core ---------------------------------------------- */
__device__ __forceinline__ int ubound256(const float* sv, float tv) {
    int lo = 0, hi = 256;
    while (lo < hi) { int m = (lo+hi) >> 1; if (sv[m] <= tv) lo = m+1; else hi = m; }
    return lo;
}

template<bool ACC>
__device__ __forceinline__ void sweep_core(const float* __restrict__ W,
        const float* sv, const int* scn, const float* tauS, const int* kcr,
        int nT, int t, float* part, float& Sout, float& Tout) {
    float S = 0.f, T = 0.f;
    int j = 0;
    for (int i0=0; i0<256; i0+=8) {
        float wv[8], vv[8];
        #pragma unroll
        for (int r=0;r<8;r++) { vv[r] = sv[i0+r]; wv[r] = W[scn[i0+r]*256 + t]; }
        #pragma unroll
        for (int r=0;r<8;r++) {
            while (j < nT && kcr[j] == i0+r) {
                float p = 2.f*(tauS[j]*S - T);
                if (ACC) part[j*256+t] += p; else part[j*256+t] = p;
                j++;
            }
            S += wv[r];
            T = fmaf(wv[r], vv[r], T);
        }
    }
    while (j < nT) {
        float p = 2.f*(tauS[j]*S - T);
        if (ACC) part[j*256+t] += p; else part[j*256+t] = p;
        j++;
    }
    Sout = S; Tout = T;
}

/* ======================================================================== */
/* k_sweep : exact GEMM1 via sorted prefix sweep. Block = one h.            */
/* ======================================================================== */
#define SWEEP_SMEM ((96*256 + 256 + 96 + 256 + 96 + 96) * 4)

__global__ __launch_bounds__(256) void k_sweep(const float* __restrict__ b1,
                                               int nHc, int nLc) {
    extern __shared__ float shraw[];
    float* part = shraw;                  /* [96][256] partials */
    float* sv   = part + 96*256;          /* sorted values      */
    float* tauS = sv + 256;               /* sorted tau         */
    int*   scn  = (int*)(tauS + 96);      /* channel perm       */
    int*   wor  = scn + 256;              /* original w of tau  */
    int*   kcr  = wor + 96;               /* crossing counts    */

    const int h = blockIdx.x, t = threadIdx.x;
    const float bias = b1[t];
    float s1 = 0.f, q1 = 0.f;

    /* ===== L side : sum of m0-sweep (W rows 0..255) + m1-sweep (256..511) */
    if (nLc > 0) {
        if (t < nLc) { tauS[t] = g_tsort[nHc + t]; wor[t] = g_tperm[nHc + t]; }
        sv[t]  = g_sv [(1*N0 + h)*256 + t];
        scn[t] = g_scn[(1*N0 + h)*256 + t];
        __syncthreads();
        if (t < nLc) kcr[t] = ubound256(sv, tauS[t]);
        __syncthreads();
        float S0, T0;
        sweep_core<false>(g_W1t, sv, scn, tauS, kcr, nLc, t, part, S0, T0);
        __syncthreads();
        sv[t]  = g_sv [(2*N0 + h)*256 + t];
        scn[t] = g_scn[(2*N0 + h)*256 + t];
        __syncthreads();
        if (t < nLc) kcr[t] = ubound256(sv, tauS[t]);
        __syncthreads();
        float S1, T1;
        sweep_core<true>(g_W1t + 256*256, sv, scn, tauS, kcr, nLc, t, part, S1, T1);
        float Ttot = T0 + T1, Stot = S0 + S1;
        for (int j=0;j<nLc;j++) {
            float r = part[j*256+t] + Ttot - tauS[j]*Stot + bias;
            r = fmaxf(r, 0.f);
            g_c1[(size_t)(h*W96 + nHc + wor[j])*256 + t] = r;
            s1 += r; q1 += r*r;
        }
        __syncthreads();
    }

    /* ===== H side : x-sweep (W rows 0..255) + exact rank-1 u*tau ===== */
    if (nHc > 0) {
        if (t < nHc) { tauS[t] = g_tsort[t]; wor[t] = g_tperm[t]; }
        sv[t]  = g_sv [h*256 + t];
        scn[t] = g_scn[h*256 + t];
        __syncthreads();
        if (t < nHc) kcr[t] = ubound256(sv, tauS[t]);
        __syncthreads();
        float S, T;
        sweep_core<false>(g_W1t, sv, scn, tauS, kcr, nHc, t, part, S, T);
        const float uo = g_u[h*D + t];
        for (int j=0;j<nHc;j++) {
            float tv = tauS[j];
            float r = part[j*256+t] + T - tv*S + uo*tv + bias;
            r = fmaxf(r, 0.f);
            g_c1[(size_t)(h*W96 + wor[j])*256 + t] = r;
            s1 += r; q1 += r*r;
        }
    }

    atomicAdd(&g_sum1[t], s1);
    atomicAdd(&g_sq1[t], q1);
}

/* ---------------- fold BN1 affine into W2 (tf32) -------------------------- */
__global__ void k_fold(const float* __restrict__ W2, const float* __restrict__ b2,
                       const float* __restrict__ g1, const float* __restrict__ bb1) {
    __shared__ float al[D], be[D];
    int t = threadIdx.x;
    float mean = g_sum1[t] * (1.f/NPIX);
    float var  = g_sq1[t]  * (1.f/NPIX) - mean*mean;
    float a    = g1[t] * rsqrtf(var + 1e-5f);
    al[t] = a; be[t] = bb1[t] - mean*a;
    __syncthreads();
    for (int v=t; v<H2*D; v+=256) {
        int c = v & 255;
        g_W2p[v] = f2tf(W2[v] * al[c]);
    }
    if (t < H2) {
        float s = b2[t];
        for (int c=0;c<D;c++) s += W2[t*D + c] * be[c];
        g_b2p[t] = s;
    }
}

/* ======================================================================== */
/* Tensor-core GEMM2 : M=128, K=256, N=144000. c1 is [pix][k] now.          */
/* ======================================================================== */
#define SPAD 36
__global__ __launch_bounds__(256,2) void k_gemm2(float* __restrict__ out) {
    const int tid = threadIdx.x;
    const int wid = tid >> 5, lane = tid & 31;
    const int wm = wid >> 2, wn = wid & 3;
    const int g = lane >> 2, tig = lane & 3;
    const int pb = blockIdx.x * 128;

    __shared__ unsigned As[128*SPAD];
    __shared__ unsigned Bs[128*SPAD];

    float c[4][4][4];
    #pragma unroll
    for (int i=0;i<4;i++) for (int j=0;j<4;j++) for (int k=0;k<4;k++) c[i][j][k]=0.f;

    const int sm = tid >> 1;
    const int sk = (tid & 1) * 16;

    for (int kc=0; kc<256; kc+=32) {
        #pragma unroll
        for (int q=0;q<4;q++)
            *(uint4*)&As[sm*SPAD + sk + q*4] =
                *(const uint4*)&g_W2p[sm*256 + kc + sk + q*4];
        #pragma unroll
        for (int q=0;q<4;q++) {
            float4 v = *(const float4*)&g_c1[(size_t)(pb+sm)*256 + kc + sk + q*4];
            uint4 o4;
            o4.x = f2tf(v.x); o4.y = f2tf(v.y); o4.z = f2tf(v.z); o4.w = f2tf(v.w);
            *(uint4*)&Bs[sm*SPAD + sk + q*4] = o4;
        }
        __syncthreads();
        #pragma unroll
        for (int ks=0; ks<4; ks++) {
            const int kk = ks*8;
            unsigned af[4][4], bf[4][2];
            #pragma unroll
            for (int mt=0;mt<4;mt++) {
                int rb = (wm*64 + mt*16 + g)*SPAD + kk + tig;
                af[mt][0]=As[rb]; af[mt][1]=As[rb+8*SPAD];
                af[mt][2]=As[rb+4]; af[mt][3]=As[rb+8*SPAD+4];
            }
            #pragma unroll
            for (int nt=0;nt<4;nt++) {
                int cb = (wn*32 + nt*8 + g)*SPAD + kk + tig;
                bf[nt][0]=Bs[cb]; bf[nt][1]=Bs[cb+4];
            }
            #pragma unroll
            for (int mt=0;mt<4;mt++)
                #pragma unroll
                for (int nt=0;nt<4;nt++)
                    mma8(c[mt][nt], af[mt][0],af[mt][1],af[mt][2],af[mt][3],
                         bf[nt][0], bf[nt][1]);
        }
        __syncthreads();
    }

    #pragma unroll
    for (int mt=0;mt<4;mt++) {
        #pragma unroll
        for (int half=0; half<2; half++) {
            int o = wm*64 + mt*16 + g + half*8;
            float bias = g_b2p[o];
            float s = 0.f, q = 0.f;
            #pragma unroll
            for (int nt=0;nt<4;nt++) {
                int n = pb + wn*32 + nt*8 + tig*2;
                float r0 = fmaxf(c[mt][nt][half*2+0] + bias, 0.f);
                float r1 = fmaxf(c[mt][nt][half*2+1] + bias, 0.f);
                *(float2*)&out[(size_t)o*NPIX + n] = make_float2(r0, r1);
                s += r0 + r1; q += r0*r0 + r1*r1;
            }
            s += __shfl_down_sync(0xffffffffu, s, 2, 4);
            s += __shfl_down_sync(0xffffffffu, s, 1, 4);
            q += __shfl_down_sync(0xffffffffu, q, 2, 4);
            q += __shfl_down_sync(0xffffffffu, q, 1, 4);
            if (tig == 0) { atomicAdd(&g_sum2[o], s); atomicAdd(&g_sq2[o], q); }
        }
    }
}

__global__ void k_ab2(const float* __restrict__ g2, const float* __restrict__ bb2) {
    int t = threadIdx.x;
    float mean = g_sum2[t]*(1.f/NPIX);
    float var  = g_sq2[t]*(1.f/NPIX) - mean*mean;
    float a    = g2[t]*rsqrtf(var + 1e-5f);
    g_a2[t] = a; g_be2[t] = bb2[t] - mean*a;
}

/* ---------------- final BN2 affine in place ------------------------------- */
__global__ void k_final(float* __restrict__ out) {
    size_t idx = (size_t)blockIdx.x*256 + threadIdx.x;
    size_t i4  = idx * 4;
    int c = (int)(i4 / NPIX);
    float a = g_a2[c], b = g_be2[c];
    float4 v = *(float4*)(out + i4);
    v.x = fmaf(a, v.x, b); v.y = fmaf(a, v.y, b);
    v.z = fmaf(a, v.z, b); v.w = fmaf(a, v.w, b);
    *(float4*)(out + i4) = v;
}

/* ---------------- launch -------------------------------------------------- */
extern "C" void kernel_launch(void* const* d_in, const int* in_sizes, int n_in,
                              void* d_out, int out_size) {
    const float* z0  = (const float*)d_in[0];
    const float* z1  = (const float*)d_in[1];
    const float* w1  = (const float*)d_in[2];
    const float* w2  = (const float*)d_in[3];
    const float* w3  = (const float*)d_in[4];
    const float* w4  = (const float*)d_in[5];
    const float* w5  = (const float*)d_in[6];
    const float* W1  = (const float*)d_in[7];
    const float* b1  = (const float*)d_in[8];
    const float* g1  = (const float*)d_in[9];
    const float* bb1 = (const float*)d_in[10];
    const float* W2  = (const float*)d_in[11];
    const float* b2  = (const float*)d_in[12];
    const float* g2  = (const float*)d_in[13];
    const float* bb2 = (const float*)d_in[14];
    const int* cdrH = (const int*)d_in[16];
    const int* cdrL = (const int*)d_in[17];
    const int* notH = (const int*)d_in[18];
    const int* notL = (const int*)d_in[19];
    int nHc = in_sizes[16], nLc = in_sizes[17];
    int nHn = in_sizes[18], nLn = in_sizes[19];
    float* out = (float*)d_out;

    static int smem_set = 0;
    if (!smem_set) {
        cudaFuncSetAttribute(k_sweep, cudaFuncAttributeMaxDynamicSharedMemorySize,
                             SWEEP_SMEM);
        smem_set = 1;
    }

    k_zero  <<<1, 256>>>();
    k_tr    <<<512, 256>>>(W1);
    k_accum <<<90, 256>>>(z0, z1);
    k_prep  <<<1, 256>>>(z1, w1, w2, w3, w4, w5, cdrH, cdrL, notH, notL,
                         nHc, nLc, nHn, nLn);
    k_pre2  <<<N0/HB, 256>>>(z0, nHc);
    k_sort  <<<dim3(N0, 3), 256>>>();
    k_sweep <<<N0, 256, SWEEP_SMEM>>>(b1, nHc, nLc);
    k_fold  <<<1, 256>>>(W2, b2, g1, bb1);
    k_gemm2 <<<NPIX/128, 256>>>(out);
    k_ab2   <<<1, 128>>>(g2, bb2);
    k_final <<<18000, 256>>>(out);
}

// round 6
// speedup vs baseline: 1.1731x; 1.1731x over previous
#include <cuda_runtime.h>
#include <math.h>

#define D     256
#define N0    1500
#define N1    1200
#define CATC  600
#define W96   96
#define NPIX  (N0*W96)      /* 144000 */
#define HID   256
#define H2    128

/* ---------------- device scratch ----------------------------------------- */
__device__ float    g_s0[D];
__device__ float    g_acc0[D];
__device__ float    g_accH[D];
__device__ float    g_accL[D];
__device__ float    g_t[W96];
__device__ float    g_tsort[W96];
__device__ int      g_tperm[W96];
__device__ float    g_meanH;
__device__ float    g_W1t[512*256];     /* W1 [k][o] fp32                   */
__device__ float    g_x [N0*D];
__device__ float    g_m0[N0*D];
__device__ float    g_m1[N0*D];
__device__ float    g_u [N0*D];
__device__ float    g_sv [3*N0*256];    /* sorted x/m0/m1 values            */
__device__ int      g_scn[3*N0*256];    /* channel perm of the sort         */
__device__ float    g_c1[(size_t)NPIX*HID];  /* relu(conv1) [pix][o]        */
__device__ float    g_sum1[HID];
__device__ float    g_sq1[HID];
__device__ float    g_sum2[H2];
__device__ float    g_sq2[H2];
__device__ unsigned g_W2p[H2*D];        /* folded W2 [o][c] tf32 bits       */
__device__ float    g_b2p[H2];
__device__ float    g_a2[H2];
__device__ float    g_be2[H2];

__device__ __forceinline__ float sigm(float v) { return 1.f/(1.f+expf(-v)); }
__device__ __forceinline__ unsigned f2tf(float f) {
    unsigned u; asm("cvt.rna.tf32.f32 %0, %1;" : "=r"(u) : "f"(f)); return u;
}
__device__ __forceinline__ void mma8(float c[4], unsigned a0, unsigned a1,
                                     unsigned a2, unsigned a3,
                                     unsigned b0, unsigned b1) {
    asm("mma.sync.aligned.m16n8k8.row.col.f32.tf32.tf32.f32 "
        "{%0,%1,%2,%3},{%4,%5,%6,%7},{%8,%9},{%0,%1,%2,%3};"
        : "+f"(c[0]),"+f"(c[1]),"+f"(c[2]),"+f"(c[3])
        : "r"(a0),"r"(a1),"r"(a2),"r"(a3),"r"(b0),"r"(b1));
}

/* ---------------- zero accumulators -------------------------------------- */
__global__ void k_zero() {
    int t = threadIdx.x;
    g_acc0[t]=0.f; g_accH[t]=0.f; g_accL[t]=0.f;
    g_sum1[t]=0.f; g_sq1[t]=0.f;
    if (t < H2) { g_sum2[t]=0.f; g_sq2[t]=0.f; }
}

/* ---------------- transpose W1 -> [k][o] ---------------------------------- */
__global__ void k_tr(const float* __restrict__ W1) {
    int c = blockIdx.x, o = threadIdx.x;
    g_W1t[c*256 + o] = W1[o*512 + c];
}

/* ---------------- channel-mean accumulation ------------------------------- */
__global__ void k_accum(const float* __restrict__ z0, const float* __restrict__ z1) {
    int b = blockIdx.x, c = threadIdx.x;
    float acc = 0.f;
    if (b < 50) {
        int r0 = b*30;
        #pragma unroll 6
        for (int i=0;i<30;i++) acc += z0[(r0+i)*D + c];
        atomicAdd(&g_acc0[c], acc);
    } else {
        int r0 = (b-50)*30;
        #pragma unroll 6
        for (int i=0;i<30;i++) acc += z1[(r0+i)*D + c];
        if (r0 < CATC) atomicAdd(&g_accH[c], acc);
        else           atomicAdd(&g_accL[c], acc);
    }
}

/* ---------------- small prep: s0, hm, lm, meanH, sorted tau --------------- */
__global__ void k_prep(const float* __restrict__ z1,
                       const float* __restrict__ w1, const float* __restrict__ w2,
                       const float* __restrict__ w3, const float* __restrict__ w4,
                       const float* __restrict__ w5,
                       const int* __restrict__ cdrH, const int* __restrict__ cdrL,
                       const int* __restrict__ notH, const int* __restrict__ notL,
                       int nHc, int nLc, int nHn, int nLn) {
    __shared__ float y0[D];
    __shared__ float av[W96];
    __shared__ float bv[CATC];
    __shared__ float red[256];
    int t = threadIdx.x;

    y0[t] = g_acc0[t] * (1.f/N0);
    __syncthreads();
    {
        float a = 0.f;
        #pragma unroll
        for (int k=0;k<5;k++) { int cc=t+k-2; if (cc>=0 && cc<D) a += w1[k]*y0[cc]; }
        g_s0[t] = sigm(a);
    }

    float sH0;
    {
        float yh0=g_accH[0]*(1.f/CATC), yh1=g_accH[1]*(1.f/CATC), yh2=g_accH[2]*(1.f/CATC);
        sH0 = sigm(w2[2]*yh0 + w2[3]*yh1 + w2[4]*yh2);
    }
    if (t < nHc) av[t] = z1[cdrH[t]*D] * sH0;
    for (int j=t; j<nHn; j+=256) bv[j] = z1[notH[j]*D] * sH0;
    __syncthreads();
    float msumH = 0.f;
    if (t < nHc) { float ai=av[t]; for (int j=0;j<nHn;j++) msumH += fabsf(ai - bv[j]); }
    red[t] = (t<nHc)? msumH : 0.f;
    __syncthreads();
    for (int m=128;m>0;m>>=1){ if(t<m) red[t]+=red[t+m]; __syncthreads(); }
    float gH = sigm(w4[2] * red[0] / ((float)nHc*(float)nHn));
    float myhm = (t<nHc) ? gH * msumH / (float)nHn : 0.f;
    if (t < nHc) g_t[t] = myhm;
    __syncthreads();

    float sL0;
    {
        float yl0=g_accL[0]*(1.f/CATC), yl1=g_accL[1]*(1.f/CATC), yl2=g_accL[2]*(1.f/CATC);
        sL0 = sigm(w3[2]*yl0 + w3[3]*yl1 + w3[4]*yl2);
    }
    if (t < nLc) av[t] = z1[(CATC+cdrL[t])*D] * sL0;
    for (int j=t; j<nLn; j+=256) bv[j] = z1[(CATC+notL[j])*D] * sL0;
    __syncthreads();
    float msumL = 0.f;
    if (t < nLc) { float ai=av[t]; for (int j=0;j<nLn;j++) msumL += fabsf(ai - bv[j]); }
    red[t] = (t<nLc)? msumL : 0.f;
    __syncthreads();
    for (int m=128;m>0;m>>=1){ if(t<m) red[t]+=red[t+m]; __syncthreads(); }
    float gL = sigm(w5[2] * red[0] / ((float)nLc*(float)nLn));
    if (t < nLc) g_t[nHc + t] = gL * msumL / (float)nLn;
    __syncthreads();

    red[t] = myhm;
    __syncthreads();
    for (int m=128;m>0;m>>=1){ if(t<m) red[t]+=red[t+m]; __syncthreads(); }
    if (t==0) g_meanH = red[0] / (float)nHc;
    __syncthreads();

    /* rank-sort tau (stable) for both sides */
    if (t < nHc) {
        float v = g_t[t]; int r = 0;
        for (int j=0;j<nHc;j++) { float vj = g_t[j]; r += (vj < v) || (vj == v && j < t); }
        g_tsort[r] = v; g_tperm[r] = t;
    }
    if (t < nLc) {
        float v = g_t[nHc+t]; int r = 0;
        for (int j=0;j<nLc;j++) { float vj = g_t[nHc+j]; r += (vj < v) || (vj == v && j < t); }
        g_tsort[nHc+r] = v; g_tperm[nHc+r] = t;
    }
}

/* ---------------- per-h vectors x, m0, m1 and u = W1hi . x ---------------- */
#define HB 10
__global__ __launch_bounds__(256) void k_pre2(const float* __restrict__ z0, int nHc) {
    __shared__ float xsall[HB][D];
    __shared__ float ts[W96];
    const int t = threadIdx.x;
    const int hbase = blockIdx.x * HB;
    if (t < W96) ts[t] = g_t[t];
    const float s0 = g_s0[t];
    const float mh = g_meanH;
    const float inv = 1.f / (float)nHc;
    __syncthreads();
    #pragma unroll
    for (int hh=0; hh<HB; hh++) {
        int h = hbase + hh;
        float x = z0[h*D + t] * s0;
        xsall[hh][t] = x;
        g_x [h*D + t] = x;
        float s = 0.f;
        for (int k=0;k<nHc;k++) s += fabsf(x - ts[k]);
        g_m0[h*D + t] = s * inv;
        g_m1[h*D + t] = x * mh;
    }
    __syncthreads();
    float u[HB];
    #pragma unroll
    for (int hh=0;hh<HB;hh++) u[hh]=0.f;
    for (int c=0;c<D;c++) {
        float wv = g_W1t[(256+c)*256 + t];
        #pragma unroll
        for (int hh=0;hh<HB;hh++) u[hh] = fmaf(wv, xsall[hh][c], u[hh]);
    }
    #pragma unroll
    for (int hh=0;hh<HB;hh++) g_u[(hbase+hh)*D + t] = u[hh];
}

/* ---------------- bitonic sort of per-h vectors --------------------------- */
__global__ void k_sort() {
    __shared__ float v[256];
    __shared__ int   ix[256];
    const int h = blockIdx.x, which = blockIdx.y, t = threadIdx.x;
    const float* src = (which == 0) ? g_x : (which == 1) ? g_m0 : g_m1;
    v[t] = src[h*256 + t]; ix[t] = t;
    __syncthreads();
    for (int k=2;k<=256;k<<=1) {
        for (int jj=k>>1; jj>0; jj>>=1) {
            int p = t ^ jj;
            if (p > t) {
                bool asc = ((t & k) == 0);
                float a = v[t], b = v[p];
                bool sw = asc ? (a > b) : (a < b);
                if (sw) {
                    v[t] = b; v[p] = a;
                    int tmp = ix[t]; ix[t] = ix[p]; ix[p] = tmp;
                }
            }
            __syncthreads();
        }
    }
    g_sv [(which*N0 + h)*256 + t] = v[t];
    g_scn[(which*N0 + h)*256 + t] = ix[t];
}

/* ---------------- sweep core: emit raw partials to g_c1 ------------------- */
__device__ __forceinline__ int ubound256(const float* sv, float tv) {
    int lo = 0, hi = 256;
    while (lo < hi) { int m = (lo+hi) >> 1; if (sv[m] <= tv) lo = m+1; else hi = m; }
    return lo;
}

template<bool ACC>
__device__ __forceinline__ void sweep_emit(const float* __restrict__ W,
        const float* sv, const int* scn, const float* tauS, const int* kcr,
        const int* wor, int nT, int t, float* __restrict__ outb,
        float& Sout, float& Tout) {
    float S = 0.f, T = 0.f;
    int j = 0;
    for (int i0=0; i0<256; i0+=8) {
        float wv[8], vv[8];
        #pragma unroll
        for (int r=0;r<8;r++) { vv[r] = sv[i0+r]; wv[r] = W[scn[i0+r]*256 + t]; }
        #pragma unroll
        for (int r=0;r<8;r++) {
            while (j < nT && kcr[j] == i0+r) {
                float p = 2.f*(tauS[j]*S - T);
                float* pp = outb + wor[j]*256 + t;
                if (ACC) *pp += p; else *pp = p;
                j++;
            }
            S += wv[r];
            T = fmaf(wv[r], vv[r], T);
        }
    }
    while (j < nT) {
        float p = 2.f*(tauS[j]*S - T);
        float* pp = outb + wor[j]*256 + t;
        if (ACC) *pp += p; else *pp = p;
        j++;
    }
    Sout = S; Tout = T;
}

/* ======================================================================== */
/* k_sweep : exact GEMM1 via sorted prefix sweep. Block = one h.            */
/* Partials staged in g_c1 (same-thread write/read) -> ~3KB smem.           */
/* ======================================================================== */
__global__ __launch_bounds__(256) void k_sweep(const float* __restrict__ b1,
                                               int nHc, int nLc) {
    __shared__ float sv[256];
    __shared__ float tauS[W96];
    __shared__ int   scn[256];
    __shared__ int   wor[W96];
    __shared__ int   kcr[W96];

    const int h = blockIdx.x, t = threadIdx.x;
    const float bias = b1[t];
    float s1 = 0.f, q1 = 0.f;

    /* ===== L side : m0-sweep (W rows 0..255) + m1-sweep (256..511) ===== */
    if (nLc > 0) {
        float* outb = g_c1 + (size_t)(h*W96 + nHc)*256;
        if (t < nLc) { tauS[t] = g_tsort[nHc + t]; wor[t] = g_tperm[nHc + t]; }
        sv[t]  = g_sv [(1*N0 + h)*256 + t];
        scn[t] = g_scn[(1*N0 + h)*256 + t];
        __syncthreads();
        if (t < nLc) kcr[t] = ubound256(sv, tauS[t]);
        __syncthreads();
        float S0, T0;
        sweep_emit<false>(g_W1t, sv, scn, tauS, kcr, wor, nLc, t, outb, S0, T0);
        __syncthreads();
        sv[t]  = g_sv [(2*N0 + h)*256 + t];
        scn[t] = g_scn[(2*N0 + h)*256 + t];
        __syncthreads();
        if (t < nLc) kcr[t] = ubound256(sv, tauS[t]);
        __syncthreads();
        float S1, T1;
        sweep_emit<true>(g_W1t + 256*256, sv, scn, tauS, kcr, wor, nLc, t, outb, S1, T1);
        float Ttot = T0 + T1, Stot = S0 + S1;
        for (int j=0;j<nLc;j++) {
            float* pp = outb + wor[j]*256 + t;
            float r = *pp + Ttot - tauS[j]*Stot + bias;
            r = fmaxf(r, 0.f);
            *pp = r;
            s1 += r; q1 += r*r;
        }
        __syncthreads();
    }

    /* ===== H side : x-sweep (W rows 0..255) + exact rank-1 u*tau ===== */
    if (nHc > 0) {
        float* outb = g_c1 + (size_t)(h*W96)*256;
        if (t < nHc) { tauS[t] = g_tsort[t]; wor[t] = g_tperm[t]; }
        sv[t]  = g_sv [h*256 + t];
        scn[t] = g_scn[h*256 + t];
        __syncthreads();
        if (t < nHc) kcr[t] = ubound256(sv, tauS[t]);
        __syncthreads();
        float S, T;
        sweep_emit<false>(g_W1t, sv, scn, tauS, kcr, wor, nHc, t, outb, S, T);
        const float uo = g_u[h*D + t];
        for (int j=0;j<nHc;j++) {
            float tv = tauS[j];
            float* pp = outb + wor[j]*256 + t;
            float r = *pp + T - tv*S + uo*tv + bias;
            r = fmaxf(r, 0.f);
            *pp = r;
            s1 += r; q1 += r*r;
        }
    }

    atomicAdd(&g_sum1[t], s1);
    atomicAdd(&g_sq1[t], q1);
}

/* ---------------- fold BN1 affine into W2 (tf32) -------------------------- */
__global__ void k_fold(const float* __restrict__ W2, const float* __restrict__ b2,
                       const float* __restrict__ g1, const float* __restrict__ bb1) {
    __shared__ float al[D], be[D];
    int t = threadIdx.x;
    float mean = g_sum1[t] * (1.f/NPIX);
    float var  = g_sq1[t]  * (1.f/NPIX) - mean*mean;
    float a    = g1[t] * rsqrtf(var + 1e-5f);
    al[t] = a; be[t] = bb1[t] - mean*a;
    __syncthreads();
    for (int v=t; v<H2*D; v+=256) {
        int c = v & 255;
        g_W2p[v] = f2tf(W2[v] * al[c]);
    }
    if (t < H2) {
        float s = b2[t];
        for (int c=0;c<D;c++) s += W2[t*D + c] * be[c];
        g_b2p[t] = s;
    }
}

/* ======================================================================== */
/* Tensor-core GEMM2 : M=128, K=256, N=144000. c1 is [pix][k].              */
/* ======================================================================== */
#define SPAD 36
__global__ __launch_bounds__(256,2) void k_gemm2(float* __restrict__ out) {
    const int tid = threadIdx.x;
    const int wid = tid >> 5, lane = tid & 31;
    const int wm = wid >> 2, wn = wid & 3;
    const int g = lane >> 2, tig = lane & 3;
    const int pb = blockIdx.x * 128;

    __shared__ unsigned As[128*SPAD];
    __shared__ unsigned Bs[128*SPAD];

    float c[4][4][4];
    #pragma unroll
    for (int i=0;i<4;i++) for (int j=0;j<4;j++) for (int k=0;k<4;k++) c[i][j][k]=0.f;

    const int sm = tid >> 1;
    const int sk = (tid & 1) * 16;

    for (int kc=0; kc<256; kc+=32) {
        #pragma unroll
        for (int q=0;q<4;q++)
            *(uint4*)&As[sm*SPAD + sk + q*4] =
                *(const uint4*)&g_W2p[sm*256 + kc + sk + q*4];
        #pragma unroll
        for (int q=0;q<4;q++) {
            float4 v = *(const float4*)&g_c1[(size_t)(pb+sm)*256 + kc + sk + q*4];
            uint4 o4;
            o4.x = f2tf(v.x); o4.y = f2tf(v.y); o4.z = f2tf(v.z); o4.w = f2tf(v.w);
            *(uint4*)&Bs[sm*SPAD + sk + q*4] = o4;
        }
        __syncthreads();
        #pragma unroll
        for (int ks=0; ks<4; ks++) {
            const int kk = ks*8;
            unsigned af[4][4], bf[4][2];
            #pragma unroll
            for (int mt=0;mt<4;mt++) {
                int rb = (wm*64 + mt*16 + g)*SPAD + kk + tig;
                af[mt][0]=As[rb]; af[mt][1]=As[rb+8*SPAD];
                af[mt][2]=As[rb+4]; af[mt][3]=As[rb+8*SPAD+4];
            }
            #pragma unroll
            for (int nt=0;nt<4;nt++) {
                int cb = (wn*32 + nt*8 + g)*SPAD + kk + tig;
                bf[nt][0]=Bs[cb]; bf[nt][1]=Bs[cb+4];
            }
            #pragma unroll
            for (int mt=0;mt<4;mt++)
                #pragma unroll
                for (int nt=0;nt<4;nt++)
                    mma8(c[mt][nt], af[mt][0],af[mt][1],af[mt][2],af[mt][3],
                         bf[nt][0], bf[nt][1]);
        }
        __syncthreads();
    }

    #pragma unroll
    for (int mt=0;mt<4;mt++) {
        #pragma unroll
        for (int half=0; half<2; half++) {
            int o = wm*64 + mt*16 + g + half*8;
            float bias = g_b2p[o];
            float s = 0.f, q = 0.f;
            #pragma unroll
            for (int nt=0;nt<4;nt++) {
                int n = pb + wn*32 + nt*8 + tig*2;
                float r0 = fmaxf(c[mt][nt][half*2+0] + bias, 0.f);
                float r1 = fmaxf(c[mt][nt][half*2+1] + bias, 0.f);
                *(float2*)&out[(size_t)o*NPIX + n] = make_float2(r0, r1);
                s += r0 + r1; q += r0*r0 + r1*r1;
            }
            s += __shfl_down_sync(0xffffffffu, s, 2, 4);
            s += __shfl_down_sync(0xffffffffu, s, 1, 4);
            q += __shfl_down_sync(0xffffffffu, q, 2, 4);
            q += __shfl_down_sync(0xffffffffu, q, 1, 4);
            if (tig == 0) { atomicAdd(&g_sum2[o], s); atomicAdd(&g_sq2[o], q); }
        }
    }
}

__global__ void k_ab2(const float* __restrict__ g2, const float* __restrict__ bb2) {
    int t = threadIdx.x;
    float mean = g_sum2[t]*(1.f/NPIX);
    float var  = g_sq2[t]*(1.f/NPIX) - mean*mean;
    float a    = g2[t]*rsqrtf(var + 1e-5f);
    g_a2[t] = a; g_be2[t] = bb2[t] - mean*a;
}

/* ---------------- final BN2 affine in place ------------------------------- */
__global__ void k_final(float* __restrict__ out) {
    size_t idx = (size_t)blockIdx.x*256 + threadIdx.x;
    size_t i4  = idx * 4;
    int c = (int)(i4 / NPIX);
    float a = g_a2[c], b = g_be2[c];
    float4 v = *(float4*)(out + i4);
    v.x = fmaf(a, v.x, b); v.y = fmaf(a, v.y, b);
    v.z = fmaf(a, v.z, b); v.w = fmaf(a, v.w, b);
    *(float4*)(out + i4) = v;
}

/* ---------------- launch -------------------------------------------------- */
extern "C" void kernel_launch(void* const* d_in, const int* in_sizes, int n_in,
                              void* d_out, int out_size) {
    const float* z0  = (const float*)d_in[0];
    const float* z1  = (const float*)d_in[1];
    const float* w1  = (const float*)d_in[2];
    const float* w2  = (const float*)d_in[3];
    const float* w3  = (const float*)d_in[4];
    const float* w4  = (const float*)d_in[5];
    const float* w5  = (const float*)d_in[6];
    const float* W1  = (const float*)d_in[7];
    const float* b1  = (const float*)d_in[8];
    const float* g1  = (const float*)d_in[9];
    const float* bb1 = (const float*)d_in[10];
    const float* W2  = (const float*)d_in[11];
    const float* b2  = (const float*)d_in[12];
    const float* g2  = (const float*)d_in[13];
    const float* bb2 = (const float*)d_in[14];
    const int* cdrH = (const int*)d_in[16];
    const int* cdrL = (const int*)d_in[17];
    const int* notH = (const int*)d_in[18];
    const int* notL = (const int*)d_in[19];
    int nHc = in_sizes[16], nLc = in_sizes[17];
    int nHn = in_sizes[18], nLn = in_sizes[19];
    float* out = (float*)d_out;

    k_zero  <<<1, 256>>>();
    k_tr    <<<512, 256>>>(W1);
    k_accum <<<90, 256>>>(z0, z1);
    k_prep  <<<1, 256>>>(z1, w1, w2, w3, w4, w5, cdrH, cdrL, notH, notL,
                         nHc, nLc, nHn, nLn);
    k_pre2  <<<N0/HB, 256>>>(z0, nHc);
    k_sort  <<<dim3(N0, 3), 256>>>();
    k_sweep <<<N0, 256>>>(b1, nHc, nLc);
    k_fold  <<<1, 256>>>(W2, b2, g1, bb1);
    k_gemm2 <<<NPIX/128, 256>>>(out);
    k_ab2   <<<1, 128>>>(g2, bb2);
    k_final <<<18000, 256>>>(out);
}